// round 12
// baseline (speedup 1.0000x reference)
#include <cuda_runtime.h>
#include <cuda_bf16.h>
#include <cuda_fp16.h>
#include <mma.h>
#include <math.h>

using namespace nvcuda;

#define LLn 3600
#define NBATCH 2
#define LDK 3712
static constexpr size_t NN  = (size_t)LLn * LLn;
static constexpr size_t NNP = (size_t)LDK * LDK;
#define MU (1.0f / 7200.0f)
#define INV_C (1.0f / 6553.6f)         // 1/(d*d*0.1)

__device__ float g_K[NBATCH * NNP];
__device__ float g_rowI[NBATCH][LLn];
__device__ float g_colI[NBATCH][LLn];
__device__ float g_rowM[NBATCH][LLn];
__device__ float g_colM[NBATCH][LLn];
__device__ float g_Sq[NBATCH][256];
__device__ float g_Sr[NBATCH][256];
__device__ float g_rowMP[NBATCH][29][LDK];
__device__ float g_colMP[NBATCH][29][LDK];
__device__ float g_a[NBATCH][LLn];
__device__ float g_b[NBATCH][LLn];
// sinkhorn scratch: 30 partial blocks per batch
__device__ float g_wp[NBATCH][30][256];
__device__ float g_vp[NBATCH][30][256];
__device__ float g_sbp[NBATCH][30];
__device__ float g_sap[NBATCH][30];
__device__ float g_ab[NBATCH];
__device__ float g_bb[NBATCH];
__device__ unsigned g_cnt2[NBATCH * 32];           // separate cache lines
__device__ volatile unsigned g_gen2[NBATCH * 32];

__device__ __forceinline__ float cm_val(float kv, float ri, float ci) {
    return (kv * kv) * (ri * ci);      // bit-identical expression everywhere
}
__device__ __forceinline__ float poly_exp(float x) {
    return 1.f + x * (1.f + x * (0.5f + x * ((1.f / 6.f) + x * (1.f / 24.f))));
}

// ---------------------------------------------------------------------------
// Sq = colwise sum of Q, Sr = colwise sum of R (per batch)
__global__ __launch_bounds__(256) void sumvec_kernel(const float* __restrict__ Q,
                                                     const float* __restrict__ R) {
    int bat = blockIdx.y;
    const float* M = (blockIdx.x ? R : Q) + (size_t)bat * LLn * 256;
    int c = threadIdx.x;
    float s0 = 0.f, s1 = 0.f, s2 = 0.f, s3 = 0.f;
    for (int r = 0; r < LLn; r += 4) {
        s0 += M[(size_t)r * 256 + c];
        s1 += M[(size_t)(r + 1) * 256 + c];
        s2 += M[(size_t)(r + 2) * 256 + c];
        s3 += M[(size_t)(r + 3) * 256 + c];
    }
    float s = (s0 + s1) + (s2 + s3);
    if (blockIdx.x) g_Sr[bat][c] = s; else g_Sq[bat][c] = s;
}

// rowI_l = 1/(3600 + q_l.Sr/c) ; colI_s = 1/(3600 + r_s.Sq/c)
__global__ __launch_bounds__(256) void sums_kernel(const float* __restrict__ Q,
                                                   const float* __restrict__ R) {
    int bat = blockIdx.y, which = blockIdx.z;
    const float* M = (which ? R : Q) + (size_t)bat * LLn * 256;
    __shared__ float sv[256];
    int t = threadIdx.x, lane = t & 31, w = t >> 5;
    sv[t] = which ? g_Sq[bat][t] : g_Sr[bat][t];
    __syncthreads();
    int row = blockIdx.x * 8 + w;
    const float4* m4 = (const float4*)(M + (size_t)row * 256);
    float4 a = m4[lane], b = m4[lane + 32];
    float d = a.x * sv[4 * lane + 0] + a.y * sv[4 * lane + 1]
            + a.z * sv[4 * lane + 2] + a.w * sv[4 * lane + 3]
            + b.x * sv[128 + 4 * lane + 0] + b.y * sv[128 + 4 * lane + 1]
            + b.z * sv[128 + 4 * lane + 2] + b.w * sv[128 + 4 * lane + 3];
#pragma unroll
    for (int o = 16; o; o >>= 1) d += __shfl_down_sync(0xffffffffu, d, o);
    if (lane == 0) {
        float v = 1.0f / (3600.0f + d * INV_C);
        if (which) g_colI[bat][row] = v; else g_rowI[bat][row] = v;
    }
}

// ---------------------------------------------------------------------------
// K = exp(Q@R^T/c) via bf16 wmma (m16n16k16). Full K=256 depth resident in
// smem (bf16), single load phase, no mainloop syncs. Fused row/col maxes.
#define BF_LD 264     // padded bf16 leading dim (in elements)
__global__ __launch_bounds__(256) void gemm_maxes_kernel(const float* __restrict__ Q,
                                                         const float* __restrict__ R) {
    extern __shared__ char dsm[];
    __nv_bfloat16* As = (__nv_bfloat16*)dsm;                   // [128][BF_LD]
    __nv_bfloat16* Bs = As + 128 * BF_LD;                      // [128][BF_LD]
    float (*Cs)[132] = (float(*)[132])dsm;                     // epilogue reuse
    __shared__ float ris[128], cis[128], colred[256];

    int bat = blockIdx.z;
    int brow = blockIdx.y * 128;
    int bcol = blockIdx.x * 128;
    int t = threadIdx.x;
    int lane = t & 31;
    int wid = t >> 5;
    int wm = wid >> 2;                 // 0..1
    int wn = wid & 3;                  // 0..3
    const float* Qb = Q + (size_t)bat * LLn * 256;
    const float* Rb = R + (size_t)bat * LLn * 256;

    // load full 128x256 fp32 tiles, convert to bf16 smem
    for (int idx = t; idx < 128 * 64; idx += 256) {
        int r = idx >> 6, c4 = (idx & 63) * 4;
        int qr = brow + r; if (qr > LLn - 1) qr = LLn - 1;
        int rr = bcol + r; if (rr > LLn - 1) rr = LLn - 1;
        float4 qa = *(const float4*)(Qb + (size_t)qr * 256 + c4);
        float4 ra = *(const float4*)(Rb + (size_t)rr * 256 + c4);
        __nv_bfloat162* ap = (__nv_bfloat162*)(As + r * BF_LD + c4);
        __nv_bfloat162* bp = (__nv_bfloat162*)(Bs + r * BF_LD + c4);
        ap[0] = __floats2bfloat162_rn(qa.x, qa.y);
        ap[1] = __floats2bfloat162_rn(qa.z, qa.w);
        bp[0] = __floats2bfloat162_rn(ra.x, ra.y);
        bp[1] = __floats2bfloat162_rn(ra.z, ra.w);
    }
    __syncthreads();

    wmma::fragment<wmma::accumulator, 16, 16, 16, float> acc[4][2];
#pragma unroll
    for (int i = 0; i < 4; i++)
#pragma unroll
        for (int j = 0; j < 2; j++) wmma::fill_fragment(acc[i][j], 0.0f);

#pragma unroll 4
    for (int kk = 0; kk < 256; kk += 16) {
        wmma::fragment<wmma::matrix_a, 16, 16, 16, __nv_bfloat16, wmma::row_major> af[4];
        wmma::fragment<wmma::matrix_b, 16, 16, 16, __nv_bfloat16, wmma::col_major> bf[2];
#pragma unroll
        for (int i = 0; i < 4; i++)
            wmma::load_matrix_sync(af[i], As + (wm * 64 + i * 16) * BF_LD + kk, BF_LD);
#pragma unroll
        for (int j = 0; j < 2; j++)
            wmma::load_matrix_sync(bf[j], Bs + (wn * 32 + j * 16) * BF_LD + kk, BF_LD);
#pragma unroll
        for (int i = 0; i < 4; i++)
#pragma unroll
            for (int j = 0; j < 2; j++)
                wmma::mma_sync(acc[i][j], af[i], bf[j], acc[i][j]);
    }

    __syncthreads();   // A/B dead; reuse dsm as Cs
#pragma unroll
    for (int i = 0; i < 4; i++)
#pragma unroll
        for (int j = 0; j < 2; j++) {
#pragma unroll
            for (int e = 0; e < acc[i][j].num_elements; e++)
                acc[i][j].x[e] = poly_exp(acc[i][j].x[e] * INV_C);
            wmma::store_matrix_sync(&Cs[wm * 64 + i * 16][wn * 32 + j * 16],
                                    acc[i][j], 132, wmma::mem_row_major);
        }
    if (t < 128) {
        int r = brow + t;
        ris[t] = (r < LLn) ? g_rowI[bat][r] : 0.f;
    } else {
        int c = bcol + (t - 128);
        cis[t - 128] = (c < LLn) ? g_colI[bat][c] : 0.f;
    }
    __syncthreads();

    float* Kb = g_K + (size_t)bat * NNP;
    for (int idx = t; idx < 128 * 32; idx += 256) {
        int r = idx >> 5, c4 = (idx & 31) * 4;
        *(float4*)(Kb + (size_t)(brow + r) * LDK + bcol + c4) = *(float4*)&Cs[r][c4];
    }

#pragma unroll
    for (int rr = 0; rr < 16; rr++) {
        int r = wid * 16 + rr;
        float ri = ris[r];
        float4 v = *(float4*)&Cs[r][lane * 4];
        float m = cm_val(v.x, ri, cis[4 * lane + 0]);
        m = fmaxf(m, cm_val(v.y, ri, cis[4 * lane + 1]));
        m = fmaxf(m, cm_val(v.z, ri, cis[4 * lane + 2]));
        m = fmaxf(m, cm_val(v.w, ri, cis[4 * lane + 3]));
#pragma unroll
        for (int o = 16; o; o >>= 1) m = fmaxf(m, __shfl_down_sync(0xffffffffu, m, o));
        if (lane == 0) g_rowMP[bat][blockIdx.x][brow + r] = m;
    }
    {
        int c = t & 127;
        int r0 = (t >> 7) * 64;
        float ci = cis[c];
        float m = 0.f;
        for (int r = r0; r < r0 + 64; r++)
            m = fmaxf(m, cm_val(Cs[r][c], ris[r], ci));
        colred[t] = m;
        __syncthreads();
        if (t < 128)
            g_colMP[bat][blockIdx.y][bcol + t] = fmaxf(colred[t], colred[t + 128]);
    }
}

__global__ __launch_bounds__(256) void redmax_kernel() {
    int bat = blockIdx.y, which = blockIdx.z;
    int r = blockIdx.x * 256 + threadIdx.x;
    if (r < LLn) {
        float m = 0.f;
#pragma unroll
        for (int j = 0; j < 29; j++)
            m = fmaxf(m, which ? g_colMP[bat][j][r] : g_rowMP[bat][j][r]);
        if (which) g_colM[bat][r] = m; else g_rowM[bat][r] = m;
    }
}

// ---------------------------------------------------------------------------
// persistent low-rank sinkhorn: 60 blocks total, 30 per batch, 120 rows each.
// Q/R slabs cached as fp16 in smem. Per-batch grid barriers (30 arrivals).
__device__ __forceinline__ void gridbar_b(int bat) {
    __syncthreads();
    if (threadIdx.x == 0) {
        __threadfence();
        unsigned gen = g_gen2[bat * 32];
        if (atomicAdd(&g_cnt2[bat * 32], 1u) == 29u) {
            g_cnt2[bat * 32] = 0;
            __threadfence();
            g_gen2[bat * 32] = gen + 1;
        } else {
            while (g_gen2[bat * 32] == gen) { __nanosleep(64); }
        }
        __threadfence();
    }
    __syncthreads();
}

__global__ __launch_bounds__(256) void sinkhorn_kernel(const float* __restrict__ Q,
                                                       const float* __restrict__ R,
                                                       const float* __restrict__ bin) {
    extern __shared__ __half hsm[];          // sQh[120*256] | sRh[120*256]
    __half* sQh = hsm;
    __half* sRh = hsm + 120 * 256;
    int t = threadIdx.x, lane = t & 31, wid = t >> 5;
    int bat = blockIdx.x / 30, i = blockIdx.x % 30;
    int l0 = i * 120;
    const float* Qb = Q + (size_t)bat * LLn * 256;
    const float* Rb = R + (size_t)bat * LLn * 256;
    float E = expf(bin[0]);
    __shared__ float vec[256];
    __shared__ float xs[120];
    __shared__ float ssum;

    // cache 120 Q rows + 120 R rows as fp16
    for (int idx = t; idx < 120 * 256; idx += 256) {
        int r = idx >> 8, c = idx & 255;
        sQh[idx] = __float2half_rn(Qb[(size_t)(l0 + r) * 256 + c]);
        sRh[idx] = __float2half_rn(Rb[(size_t)(l0 + r) * 256 + c]);
    }
    __syncthreads();

    // init: b = 1 everywhere, b_bin = 1
    {
        float wp = 0.f;
        for (int r = 0; r < 120; r++) wp += __half2float(sRh[r * 256 + t]);
        g_wp[bat][i][t] = wp;
        if (t == 0) { g_sbp[bat][i] = 120.f; if (i == 0) g_bb[bat] = 1.f; }
    }
    gridbar_b(bat);

    for (int it = 0; it < 50; it++) {
        // --- Phase A: a-update + v-partials ---
        {
            float w0 = 0.f, w1 = 0.f, w2 = 0.f;
            for (int j = 0; j < 30; j += 3) {
                w0 += g_wp[bat][j][t];
                w1 += g_wp[bat][j + 1][t];
                w2 += g_wp[bat][j + 2][t];
            }
            vec[t] = w0 + w1 + w2;
            if (t == 0) {
                float s = 0.f;
                for (int j = 0; j < 30; j++) s += g_sbp[bat][j];
                ssum = s;
            }
            __syncthreads();
            float Sb = ssum, bb = g_bb[bat];
            float base = Sb + E * bb;
            for (int r = wid; r < 120; r += 8) {
                const __half2* q2 = (const __half2*)(sQh + r * 256);
                float d = 0.f;
#pragma unroll
                for (int u = 0; u < 4; u++) {
                    int p = lane + u * 32;
                    float2 f = __half22float2(q2[p]);
                    d += f.x * vec[2 * p] + f.y * vec[2 * p + 1];
                }
#pragma unroll
                for (int o = 16; o; o >>= 1) d += __shfl_down_sync(0xffffffffu, d, o);
                if (lane == 0) {
                    float a = MU / (base + d * INV_C);
                    xs[r] = a;
                    g_a[bat][l0 + r] = a;
                }
            }
            if (t == 0 && i == 0) g_ab[bat] = 0.5f / (E * (Sb + bb));
            __syncthreads();
            float vp = 0.f;
            for (int r = 0; r < 120; r++)
                vp += __half2float(sQh[r * 256 + t]) * xs[r];
            g_vp[bat][i][t] = vp;
            if (t == 0) {
                float s = 0.f;
                for (int r = 0; r < 120; r++) s += xs[r];
                g_sap[bat][i] = s;
            }
        }
        gridbar_b(bat);
        // --- Phase B: b-update + w-partials ---
        {
            float w0 = 0.f, w1 = 0.f, w2 = 0.f;
            for (int j = 0; j < 30; j += 3) {
                w0 += g_vp[bat][j][t];
                w1 += g_vp[bat][j + 1][t];
                w2 += g_vp[bat][j + 2][t];
            }
            vec[t] = w0 + w1 + w2;
            if (t == 0) {
                float s = 0.f;
                for (int j = 0; j < 30; j++) s += g_sap[bat][j];
                ssum = s;
            }
            __syncthreads();
            float Sa = ssum, ab = g_ab[bat];
            float base = Sa + E * ab;
            for (int r = wid; r < 120; r += 8) {
                const __half2* r2 = (const __half2*)(sRh + r * 256);
                float d = 0.f;
#pragma unroll
                for (int u = 0; u < 4; u++) {
                    int p = lane + u * 32;
                    float2 f = __half22float2(r2[p]);
                    d += f.x * vec[2 * p] + f.y * vec[2 * p + 1];
                }
#pragma unroll
                for (int o = 16; o; o >>= 1) d += __shfl_down_sync(0xffffffffu, d, o);
                if (lane == 0) {
                    float bv = MU / (base + d * INV_C);
                    xs[r] = bv;
                    g_b[bat][l0 + r] = bv;
                }
            }
            if (t == 0 && i == 0) g_bb[bat] = 0.5f / (E * (Sa + ab));
            __syncthreads();
            float wp = 0.f;
            for (int r = 0; r < 120; r++)
                wp += __half2float(sRh[r * 256 + t]) * xs[r];
            g_wp[bat][i][t] = wp;
            if (t == 0) {
                float s = 0.f;
                for (int r = 0; r < 120; r++) s += xs[r];
                g_sbp[bat][i] = s;
            }
        }
        gridbar_b(bat);
    }
}

// ---------------------------------------------------------------------------
// out0 = cm, out1 = cf (mutual max), out2 = K*a*b*7200
__global__ __launch_bounds__(256) void final_kernel(float* __restrict__ out) {
    int b = blockIdx.y;
    __shared__ float sc[LLn];
    __shared__ float smx[LLn];
    __shared__ float sb[LLn];
    int t = threadIdx.x, lane = t & 31, w = t >> 5;
    for (int i = t; i < LLn; i += 256) {
        sc[i]  = g_colI[b][i];
        smx[i] = g_colM[b][i];
        sb[i]  = g_b[b][i];
    }
    __syncthreads();
    int row = blockIdx.x * 8 + w;
    float ri  = g_rowI[b][row];
    float rmx = g_rowM[b][row];
    float av  = g_a[b][row] * 7200.0f;
    const float4* Kr4 = (const float4*)(g_K + (size_t)b * NNP + (size_t)row * LDK);
    size_t obase = (size_t)b * NN + (size_t)row * LLn;
    float4* o0 = (float4*)(out + obase);
    float4* o1 = (float4*)(out + (size_t)NBATCH * NN + obase);
    float4* o2 = (float4*)(out + (size_t)2 * NBATCH * NN + obase);
    for (int i = lane; i < 900; i += 32) {
        float4 kv = Kr4[i];
        float4 c, f, s;
        c.x = cm_val(kv.x, ri, sc[4 * i + 0]);
        c.y = cm_val(kv.y, ri, sc[4 * i + 1]);
        c.z = cm_val(kv.z, ri, sc[4 * i + 2]);
        c.w = cm_val(kv.w, ri, sc[4 * i + 3]);
        f.x = (c.x == rmx && c.x == smx[4 * i + 0]) ? c.x : 0.f;
        f.y = (c.y == rmx && c.y == smx[4 * i + 1]) ? c.y : 0.f;
        f.z = (c.z == rmx && c.z == smx[4 * i + 2]) ? c.z : 0.f;
        f.w = (c.w == rmx && c.w == smx[4 * i + 3]) ? c.w : 0.f;
        s.x = kv.x * av * sb[4 * i + 0];
        s.y = kv.y * av * sb[4 * i + 1];
        s.z = kv.z * av * sb[4 * i + 2];
        s.w = kv.w * av * sb[4 * i + 3];
        o0[i] = c;
        o1[i] = f;
        o2[i] = s;
    }
}

extern "C" void kernel_launch(void* const* d_in, const int* in_sizes, int n_in,
                              void* d_out, int out_size) {
    const float* Q   = (const float*)d_in[0];
    const float* R   = (const float*)d_in[1];
    const float* bin = (const float*)d_in[2];
    float* out = (float*)d_out;

    static int gemm_smem = 2 * 128 * BF_LD * 2;     // 135168 B
    static int skh_smem  = 2 * 120 * 256 * 2;       // 122880 B
    cudaFuncSetAttribute(gemm_maxes_kernel,
                         cudaFuncAttributeMaxDynamicSharedMemorySize, gemm_smem);
    cudaFuncSetAttribute(sinkhorn_kernel,
                         cudaFuncAttributeMaxDynamicSharedMemorySize, skh_smem);

    sumvec_kernel<<<dim3(2, NBATCH), 256>>>(Q, R);
    sums_kernel<<<dim3(450, NBATCH, 2), 256>>>(Q, R);
    gemm_maxes_kernel<<<dim3(29, 29, NBATCH), 256, gemm_smem>>>(Q, R);
    redmax_kernel<<<dim3(15, NBATCH, 2), 256>>>();
    sinkhorn_kernel<<<60, 256, skh_smem>>>(Q, R, bin);
    final_kernel<<<dim3(450, NBATCH), 256>>>(out);
}

// round 14
// speedup vs baseline: 1.0050x; 1.0050x over previous
#include <cuda_runtime.h>
#include <mma.h>
#include <math.h>

using namespace nvcuda;

#define LLn 3600
#define NBATCH 2
#define LDK 3712
static constexpr size_t NN  = (size_t)LLn * LLn;
static constexpr size_t NNP = (size_t)LDK * LDK;
#define MU (1.0f / 7200.0f)
#define INV_C (1.0f / 6553.6f)         // 1/(d*d*0.1)

__device__ float g_K[NBATCH * NNP];
__device__ float g_rowI[NBATCH][LLn];
__device__ float g_colI[NBATCH][LLn];
__device__ float g_rowM[NBATCH][LLn];
__device__ float g_colM[NBATCH][LLn];
__device__ float g_Sq[NBATCH][256];
__device__ float g_Sr[NBATCH][256];
__device__ float g_rowMP[NBATCH][29][LDK];
__device__ float g_colMP[NBATCH][29][LDK];
__device__ float g_a[NBATCH][LLn];
__device__ float g_b[NBATCH][LLn];
// sinkhorn scratch: 60 partial blocks per batch
__device__ float g_wp[NBATCH][60][256];
__device__ float g_vp[NBATCH][60][256];
__device__ float g_sbp[NBATCH][60];
__device__ float g_sap[NBATCH][60];
__device__ float g_ab[NBATCH];
__device__ float g_bb[NBATCH];
__device__ unsigned g_cnt2[NBATCH * 32];           // separate cache lines per batch
__device__ volatile unsigned g_gen2[NBATCH * 32];

__device__ __forceinline__ float cm_val(float kv, float ri, float ci) {
    return (kv * kv) * (ri * ci);      // bit-identical expression everywhere
}
__device__ __forceinline__ float poly_exp(float x) {
    return 1.f + x * (1.f + x * (0.5f + x * ((1.f / 6.f) + x * (1.f / 24.f))));
}

// ---------------------------------------------------------------------------
// Sq = colwise sum of Q, Sr = colwise sum of R (per batch)
__global__ __launch_bounds__(256) void sumvec_kernel(const float* __restrict__ Q,
                                                     const float* __restrict__ R) {
    int bat = blockIdx.y;
    const float* M = (blockIdx.x ? R : Q) + (size_t)bat * LLn * 256;
    int c = threadIdx.x;
    float s0 = 0.f, s1 = 0.f, s2 = 0.f, s3 = 0.f;
    for (int r = 0; r < LLn; r += 4) {
        s0 += M[(size_t)r * 256 + c];
        s1 += M[(size_t)(r + 1) * 256 + c];
        s2 += M[(size_t)(r + 2) * 256 + c];
        s3 += M[(size_t)(r + 3) * 256 + c];
    }
    float s = (s0 + s1) + (s2 + s3);
    if (blockIdx.x) g_Sr[bat][c] = s; else g_Sq[bat][c] = s;
}

// rowI_l = 1/(3600 + q_l.Sr/c) ; colI_s = 1/(3600 + r_s.Sq/c)
__global__ __launch_bounds__(256) void sums_kernel(const float* __restrict__ Q,
                                                   const float* __restrict__ R) {
    int bat = blockIdx.y, which = blockIdx.z;
    const float* M = (which ? R : Q) + (size_t)bat * LLn * 256;
    __shared__ float sv[256];
    int t = threadIdx.x, lane = t & 31, w = t >> 5;
    sv[t] = which ? g_Sq[bat][t] : g_Sr[bat][t];
    __syncthreads();
    int row = blockIdx.x * 8 + w;
    const float4* m4 = (const float4*)(M + (size_t)row * 256);
    float4 a = m4[lane], b = m4[lane + 32];
    float d = a.x * sv[4 * lane + 0] + a.y * sv[4 * lane + 1]
            + a.z * sv[4 * lane + 2] + a.w * sv[4 * lane + 3]
            + b.x * sv[128 + 4 * lane + 0] + b.y * sv[128 + 4 * lane + 1]
            + b.z * sv[128 + 4 * lane + 2] + b.w * sv[128 + 4 * lane + 3];
#pragma unroll
    for (int o = 16; o; o >>= 1) d += __shfl_down_sync(0xffffffffu, d, o);
    if (lane == 0) {
        float v = 1.0f / (3600.0f + d * INV_C);
        if (which) g_colI[bat][row] = v; else g_rowI[bat][row] = v;
    }
}

// ---------------------------------------------------------------------------
// K = exp(Q@R^T/c) via tf32 wmma, double-buffered staging, fused row/col maxes.
// Dynamic smem: stages As/Bs[2][128][36] (72KB); epilogue Cs[128][132] reuse.
__global__ __launch_bounds__(256) void gemm_maxes_kernel(const float* __restrict__ Q,
                                                         const float* __restrict__ R) {
    extern __shared__ float dsm[];
    // stage s: As at dsm + s*9216, Bs at dsm + s*9216 + 4608  (128*36=4608)
    float (*Cs)[132] = (float(*)[132])dsm;
    __shared__ float ris[128], cis[128], colred[256];

    int bat = blockIdx.z;
    int brow = blockIdx.y * 128;
    int bcol = blockIdx.x * 128;
    int t = threadIdx.x;
    int lane = t & 31;
    int wid = t >> 5;
    int wm = wid >> 2;                 // 0..1
    int wn = wid & 3;                  // 0..3
    int lr = t >> 1;                   // 0..127 (row for staging)
    int c4 = (t & 1) * 16;             // 0 or 16: this thread covers cols [c4, c4+16)
    const float* Qb = Q + (size_t)bat * LLn * 256;
    const float* Rb = R + (size_t)bat * LLn * 256;
    int qrow = brow + lr; if (qrow > LLn - 1) qrow = LLn - 1;
    int rrow = bcol + lr; if (rrow > LLn - 1) rrow = LLn - 1;
    const float* qp = Qb + (size_t)qrow * 256 + c4;
    const float* rp = Rb + (size_t)rrow * 256 + c4;

    wmma::fragment<wmma::accumulator, 16, 16, 8, float> acc[4][2];
#pragma unroll
    for (int i = 0; i < 4; i++)
#pragma unroll
        for (int j = 0; j < 2; j++) wmma::fill_fragment(acc[i][j], 0.0f);

    float4 qa[4], ra[4];
    // prologue: load chunk 0 into regs, park in stage 0
#pragma unroll
    for (int u = 0; u < 4; u++) {
        qa[u] = *(const float4*)(qp + u * 4);
        ra[u] = *(const float4*)(rp + u * 4);
    }
    {
        float* As = dsm;
        float* Bs = dsm + 4608;
#pragma unroll
        for (int u = 0; u < 4; u++) {
            *(float4*)&As[lr * 36 + c4 + u * 4] = qa[u];
            *(float4*)&Bs[lr * 36 + c4 + u * 4] = ra[u];
        }
    }
    __syncthreads();

    for (int kb = 1; kb <= 8; kb++) {
        int cur = (kb - 1) & 1, nxt = kb & 1;
        if (kb < 8) {
#pragma unroll
            for (int u = 0; u < 4; u++) {
                qa[u] = *(const float4*)(qp + kb * 32 + u * 4);
                ra[u] = *(const float4*)(rp + kb * 32 + u * 4);
            }
        }
        float* As = dsm + cur * 9216;
        float* Bs = As + 4608;
#pragma unroll
        for (int kk = 0; kk < 32; kk += 8) {
            wmma::fragment<wmma::matrix_a, 16, 16, 8, wmma::precision::tf32, wmma::row_major> af[4];
            wmma::fragment<wmma::matrix_b, 16, 16, 8, wmma::precision::tf32, wmma::col_major> bf[2];
#pragma unroll
            for (int i = 0; i < 4; i++) {
                wmma::load_matrix_sync(af[i], As + (wm * 64 + i * 16) * 36 + kk, 36);
#pragma unroll
                for (int e = 0; e < af[i].num_elements; e++)
                    af[i].x[e] = wmma::__float_to_tf32(af[i].x[e]);
            }
#pragma unroll
            for (int j = 0; j < 2; j++) {
                wmma::load_matrix_sync(bf[j], Bs + (wn * 32 + j * 16) * 36 + kk, 36);
#pragma unroll
                for (int e = 0; e < bf[j].num_elements; e++)
                    bf[j].x[e] = wmma::__float_to_tf32(bf[j].x[e]);
            }
#pragma unroll
            for (int i = 0; i < 4; i++)
#pragma unroll
                for (int j = 0; j < 2; j++)
                    wmma::mma_sync(acc[i][j], af[i], bf[j], acc[i][j]);
        }
        if (kb < 8) {
            float* An = dsm + nxt * 9216;
            float* Bn = An + 4608;
#pragma unroll
            for (int u = 0; u < 4; u++) {
                *(float4*)&An[lr * 36 + c4 + u * 4] = qa[u];
                *(float4*)&Bn[lr * 36 + c4 + u * 4] = ra[u];
            }
            __syncthreads();
        }
    }

    __syncthreads();   // stages dead; reuse dsm as Cs
#pragma unroll
    for (int i = 0; i < 4; i++)
#pragma unroll
        for (int j = 0; j < 2; j++) {
#pragma unroll
            for (int e = 0; e < acc[i][j].num_elements; e++)
                acc[i][j].x[e] = poly_exp(acc[i][j].x[e] * INV_C);
            wmma::store_matrix_sync(&Cs[wm * 64 + i * 16][wn * 32 + j * 16],
                                    acc[i][j], 132, wmma::mem_row_major);
        }
    if (t < 128) {
        int r = brow + t;
        ris[t] = (r < LLn) ? g_rowI[bat][r] : 0.f;
    } else {
        int c = bcol + (t - 128);
        cis[t - 128] = (c < LLn) ? g_colI[bat][c] : 0.f;
    }
    __syncthreads();

    float* Kb = g_K + (size_t)bat * NNP;
    for (int idx = t; idx < 128 * 32; idx += 256) {
        int r = idx >> 5, cc = (idx & 31) * 4;
        *(float4*)(Kb + (size_t)(brow + r) * LDK + bcol + cc) = *(float4*)&Cs[r][cc];
    }

#pragma unroll
    for (int rr = 0; rr < 16; rr++) {
        int r = wid * 16 + rr;
        float ri = ris[r];
        float4 v = *(float4*)&Cs[r][lane * 4];
        float m = cm_val(v.x, ri, cis[4 * lane + 0]);
        m = fmaxf(m, cm_val(v.y, ri, cis[4 * lane + 1]));
        m = fmaxf(m, cm_val(v.z, ri, cis[4 * lane + 2]));
        m = fmaxf(m, cm_val(v.w, ri, cis[4 * lane + 3]));
#pragma unroll
        for (int o = 16; o; o >>= 1) m = fmaxf(m, __shfl_down_sync(0xffffffffu, m, o));
        if (lane == 0) g_rowMP[bat][blockIdx.x][brow + r] = m;
    }
    {
        int c = t & 127;
        int r0 = (t >> 7) * 64;
        float ci = cis[c];
        float m = 0.f;
        for (int r = r0; r < r0 + 64; r++)
            m = fmaxf(m, cm_val(Cs[r][c], ris[r], ci));
        colred[t] = m;
        __syncthreads();
        if (t < 128)
            g_colMP[bat][blockIdx.y][bcol + t] = fmaxf(colred[t], colred[t + 128]);
    }
}

__global__ __launch_bounds__(256) void redmax_kernel() {
    int bat = blockIdx.y, which = blockIdx.z;
    int r = blockIdx.x * 256 + threadIdx.x;
    if (r < LLn) {
        float m = 0.f;
#pragma unroll
        for (int j = 0; j < 29; j++)
            m = fmaxf(m, which ? g_colMP[bat][j][r] : g_rowMP[bat][j][r]);
        if (which) g_colM[bat][r] = m; else g_rowM[bat][r] = m;
    }
}

// ---------------------------------------------------------------------------
// persistent low-rank sinkhorn: 120 blocks, 60 per batch, 60 rows each.
// Q/R slabs cached fp32 in smem; per-batch grid barriers (60 arrivals).
__device__ __forceinline__ void gridbar_b(int bat) {
    __syncthreads();
    if (threadIdx.x == 0) {
        __threadfence();
        unsigned gen = g_gen2[bat * 32];
        if (atomicAdd(&g_cnt2[bat * 32], 1u) == 59u) {
            g_cnt2[bat * 32] = 0;
            __threadfence();
            g_gen2[bat * 32] = gen + 1;
        } else {
            while (g_gen2[bat * 32] == gen) { __nanosleep(64); }
        }
        __threadfence();
    }
    __syncthreads();
}

__global__ __launch_bounds__(256) void sinkhorn_kernel(const float* __restrict__ Q,
                                                       const float* __restrict__ R,
                                                       const float* __restrict__ bin) {
    extern __shared__ float tile[];          // sQ[60*256] | sR[60*256]
    float* sQ = tile;
    float* sR = tile + 60 * 256;
    int t = threadIdx.x, lane = t & 31, wid = t >> 5;
    int bat = blockIdx.x / 60, i = blockIdx.x % 60;
    int l0 = i * 60;
    const float* Qb = Q + (size_t)bat * LLn * 256;
    const float* Rb = R + (size_t)bat * LLn * 256;
    float E = expf(bin[0]);
    __shared__ float vec[256];
    __shared__ float xs[60];
    __shared__ float ssum;

    // cache this block's 60 Q rows and 60 R rows
    for (int idx = t; idx < 60 * 256; idx += 256) {
        int r = idx >> 8, c = idx & 255;
        sQ[idx] = Qb[(size_t)(l0 + r) * 256 + c];
        sR[idx] = Rb[(size_t)(l0 + r) * 256 + c];
    }
    __syncthreads();

    // init: b = 1, b_bin = 1
    {
        float wp = 0.f;
        for (int r = 0; r < 60; r++) wp += sR[r * 256 + t];
        g_wp[bat][i][t] = wp;
        if (t == 0) { g_sbp[bat][i] = 60.f; if (i == 0) g_bb[bat] = 1.f; }
    }
    gridbar_b(bat);

    for (int it = 0; it < 50; it++) {
        // --- Phase A: a-update + v-partials ---
        {
            float w0 = 0.f, w1 = 0.f, w2 = 0.f, w3 = 0.f;
            for (int j = 0; j < 60; j += 4) {
                w0 += g_wp[bat][j][t];     w1 += g_wp[bat][j + 1][t];
                w2 += g_wp[bat][j + 2][t]; w3 += g_wp[bat][j + 3][t];
            }
            vec[t] = (w0 + w1) + (w2 + w3);
            if (t == 0) {
                float s = 0.f;
                for (int j = 0; j < 60; j++) s += g_sbp[bat][j];
                ssum = s;
            }
            __syncthreads();
            float Sb = ssum, bb = g_bb[bat];
            float base = Sb + E * bb;
            for (int r = wid; r < 60; r += 8) {
                const float4* q4 = (const float4*)(sQ + r * 256);
                float4 v1 = q4[lane], v2 = q4[lane + 32];
                float d = v1.x * vec[4 * lane + 0] + v1.y * vec[4 * lane + 1]
                        + v1.z * vec[4 * lane + 2] + v1.w * vec[4 * lane + 3]
                        + v2.x * vec[128 + 4 * lane + 0] + v2.y * vec[128 + 4 * lane + 1]
                        + v2.z * vec[128 + 4 * lane + 2] + v2.w * vec[128 + 4 * lane + 3];
#pragma unroll
                for (int o = 16; o; o >>= 1) d += __shfl_down_sync(0xffffffffu, d, o);
                if (lane == 0) {
                    float a = MU / (base + d * INV_C);
                    xs[r] = a;
                    g_a[bat][l0 + r] = a;
                }
            }
            if (t == 0 && i == 0) g_ab[bat] = 0.5f / (E * (Sb + bb));
            __syncthreads();
            float vp = 0.f;
            for (int r = 0; r < 60; r++) vp += sQ[r * 256 + t] * xs[r];
            g_vp[bat][i][t] = vp;
            if (t == 0) {
                float s = 0.f;
                for (int r = 0; r < 60; r++) s += xs[r];
                g_sap[bat][i] = s;
            }
        }
        gridbar_b(bat);
        // --- Phase B: b-update + w-partials ---
        {
            float w0 = 0.f, w1 = 0.f, w2 = 0.f, w3 = 0.f;
            for (int j = 0; j < 60; j += 4) {
                w0 += g_vp[bat][j][t];     w1 += g_vp[bat][j + 1][t];
                w2 += g_vp[bat][j + 2][t]; w3 += g_vp[bat][j + 3][t];
            }
            vec[t] = (w0 + w1) + (w2 + w3);
            if (t == 0) {
                float s = 0.f;
                for (int j = 0; j < 60; j++) s += g_sap[bat][j];
                ssum = s;
            }
            __syncthreads();
            float Sa = ssum, ab = g_ab[bat];
            float base = Sa + E * ab;
            for (int r = wid; r < 60; r += 8) {
                const float4* r4 = (const float4*)(sR + r * 256);
                float4 v1 = r4[lane], v2 = r4[lane + 32];
                float d = v1.x * vec[4 * lane + 0] + v1.y * vec[4 * lane + 1]
                        + v1.z * vec[4 * lane + 2] + v1.w * vec[4 * lane + 3]
                        + v2.x * vec[128 + 4 * lane + 0] + v2.y * vec[128 + 4 * lane + 1]
                        + v2.z * vec[128 + 4 * lane + 2] + v2.w * vec[128 + 4 * lane + 3];
#pragma unroll
                for (int o = 16; o; o >>= 1) d += __shfl_down_sync(0xffffffffu, d, o);
                if (lane == 0) {
                    float bv = MU / (base + d * INV_C);
                    xs[r] = bv;
                    g_b[bat][l0 + r] = bv;
                }
            }
            if (t == 0 && i == 0) g_bb[bat] = 0.5f / (E * (Sa + ab));
            __syncthreads();
            float wp = 0.f;
            for (int r = 0; r < 60; r++) wp += sR[r * 256 + t] * xs[r];
            g_wp[bat][i][t] = wp;
            if (t == 0) {
                float s = 0.f;
                for (int r = 0; r < 60; r++) s += xs[r];
                g_sbp[bat][i] = s;
            }
        }
        gridbar_b(bat);
    }
}

// ---------------------------------------------------------------------------
// out0 = cm, out1 = cf (mutual max), out2 = K*a*b*7200
__global__ __launch_bounds__(256) void final_kernel(float* __restrict__ out) {
    int b = blockIdx.y;
    __shared__ float sc[LLn];
    __shared__ float smx[LLn];
    __shared__ float sb[LLn];
    int t = threadIdx.x, lane = t & 31, w = t >> 5;
    for (int i = t; i < LLn; i += 256) {
        sc[i]  = g_colI[b][i];
        smx[i] = g_colM[b][i];
        sb[i]  = g_b[b][i];
    }
    __syncthreads();
    int row = blockIdx.x * 8 + w;
    float ri  = g_rowI[b][row];
    float rmx = g_rowM[b][row];
    float av  = g_a[b][row] * 7200.0f;
    const float4* Kr4 = (const float4*)(g_K + (size_t)b * NNP + (size_t)row * LDK);
    size_t obase = (size_t)b * NN + (size_t)row * LLn;
    float4* o0 = (float4*)(out + obase);
    float4* o1 = (float4*)(out + (size_t)NBATCH * NN + obase);
    float4* o2 = (float4*)(out + (size_t)2 * NBATCH * NN + obase);
    for (int i = lane; i < 900; i += 32) {
        float4 kv = Kr4[i];
        float4 c, f, s;
        c.x = cm_val(kv.x, ri, sc[4 * i + 0]);
        c.y = cm_val(kv.y, ri, sc[4 * i + 1]);
        c.z = cm_val(kv.z, ri, sc[4 * i + 2]);
        c.w = cm_val(kv.w, ri, sc[4 * i + 3]);
        f.x = (c.x == rmx && c.x == smx[4 * i + 0]) ? c.x : 0.f;
        f.y = (c.y == rmx && c.y == smx[4 * i + 1]) ? c.y : 0.f;
        f.z = (c.z == rmx && c.z == smx[4 * i + 2]) ? c.z : 0.f;
        f.w = (c.w == rmx && c.w == smx[4 * i + 3]) ? c.w : 0.f;
        s.x = kv.x * av * sb[4 * i + 0];
        s.y = kv.y * av * sb[4 * i + 1];
        s.z = kv.z * av * sb[4 * i + 2];
        s.w = kv.w * av * sb[4 * i + 3];
        o0[i] = c;
        o1[i] = f;
        o2[i] = s;
    }
}

extern "C" void kernel_launch(void* const* d_in, const int* in_sizes, int n_in,
                              void* d_out, int out_size) {
    const float* Q   = (const float*)d_in[0];
    const float* R   = (const float*)d_in[1];
    const float* bin = (const float*)d_in[2];
    float* out = (float*)d_out;

    int gemm_smem = 2 * 9216 * 4;               // 73728 B (>= Cs 67584)
    int skh_smem  = 2 * 60 * 256 * 4;           // 122880 B
    cudaFuncSetAttribute(gemm_maxes_kernel,
                         cudaFuncAttributeMaxDynamicSharedMemorySize, gemm_smem);
    cudaFuncSetAttribute(sinkhorn_kernel,
                         cudaFuncAttributeMaxDynamicSharedMemorySize, skh_smem);

    sumvec_kernel<<<dim3(2, NBATCH), 256>>>(Q, R);
    sums_kernel<<<dim3(450, NBATCH, 2), 256>>>(Q, R);
    gemm_maxes_kernel<<<dim3(29, 29, NBATCH), 256, gemm_smem>>>(Q, R);
    redmax_kernel<<<dim3(15, NBATCH, 2), 256>>>();
    sinkhorn_kernel<<<120, 256, skh_smem>>>(Q, R, bin);
    final_kernel<<<dim3(450, NBATCH), 256>>>(out);
}